// round 5
// baseline (speedup 1.0000x reference)
#include <cuda_runtime.h>
#include <math.h>

// Problem constants
#define NV    5000
#define NFC   10000
#define LAYERS 30
#define NNZT  480000
#define EPSBN 1e-5f
#define QF    (4*NFC)   // 40000 quaternion face rows
#define QV    (4*NV)    // 20000 quaternion vertex rows

// ---------------- device scratch ----------------
__device__ __align__(16) float g_v [NV  * 128];
__device__ __align__(16) float g_ev[NV  * 128];
__device__ __align__(16) float g_ef[NFC * 128];
__device__ __align__(16) float g_ex[NV  * 128];
__device__ __align__(16) float g_Dv[NFC * 128];
__device__ __align__(16) float g_DA[NV  * 128];
__device__ float g_stats[64 * 512];
__device__ float g_a   [128];
__device__ float g_bout[1];
// CSR scratch (built once per launch, used 15x each)
__device__ int   g_rp0[QF + 1];
__device__ int   g_rp1[QV + 1];
__device__ int   g_pc0[NNZT];
__device__ int   g_pc1[NNZT];
__device__ float g_pv0[NNZT];
__device__ float g_pv1[NNZT];
__device__ int   g_cnt[QF + 1];

__device__ __forceinline__ float eluf(float x) {
    return x > 0.f ? x : (__expf(x) - 1.f);
}

// ---------------- input projection ----------------
__global__ void k_in(const float* __restrict__ in, const float* __restrict__ Wi,
                     const float* __restrict__ bi, float* __restrict__ statp) {
    int c = threadIdx.x;  // 128
    float w0 = Wi[c], w1 = Wi[128 + c], w2 = Wi[256 + c], b = bi[c];
    float s = 0.f, s2 = 0.f;
    for (int n = blockIdx.x; n < NV; n += gridDim.x) {
        float val = b + in[n * 3] * w0 + in[n * 3 + 1] * w1 + in[n * 3 + 2] * w2;
        g_v [n * 128 + c] = val;
        float e = eluf(val);
        g_ev[n * 128 + c] = e;
        s += e; s2 += e * e;
    }
    atomicAdd(&statp[c], s);
    atomicAdd(&statp[256 + c], s2);
}

// ---------------- CSR build ----------------
__global__ void k_hist(const int* __restrict__ rows_, int* __restrict__ cnt) {
    int e = blockIdx.x * blockDim.x + threadIdx.x;
    if (e < NNZT) atomicAdd(&cnt[rows_[e]], 1);
}

// exclusive scan (1 block, 1024 threads): cnt[0..n) -> rp[0..n], rp[n]=total; cnt <- cursors
__global__ void k_scan(int* __restrict__ cnt, int* __restrict__ rp, int n) {
    __shared__ int part[1024];
    int tid = threadIdx.x;
    int per = (n + 1023) / 1024;
    int s0 = tid * per;
    int s1 = s0 + per < n ? s0 + per : n;
    int local = 0;
    for (int i = s0; i < s1; i++) local += cnt[i];
    part[tid] = local;
    __syncthreads();
    for (int off = 1; off < 1024; off <<= 1) {
        int v = part[tid];
        int u = (tid >= off) ? part[tid - off] : 0;
        __syncthreads();
        part[tid] = v + u;
        __syncthreads();
    }
    int run = (tid == 0) ? 0 : part[tid - 1];
    for (int i = s0; i < s1; i++) {
        int c = cnt[i];
        rp[i] = run;
        run += c;
    }
    if (tid == 0) rp[n] = part[1023];
    __syncthreads();
    for (int i = s0; i < s1; i++) cnt[i] = rp[i];
}

__global__ void k_scatter(const int* __restrict__ rows_, const int* __restrict__ cols_,
                          const float* __restrict__ vals, int* __restrict__ cur,
                          int* __restrict__ pc, float* __restrict__ pv) {
    int e = blockIdx.x * blockDim.x + threadIdx.x;
    if (e >= NNZT) return;
    int p = atomicAdd(&cur[rows_[e]], 1);
    pc[p] = cols_[e];
    pv[p] = vals[e];
}

// ---------------- CSR spMM: warp per quaternion row, atomic-free ----------------
__global__ void k_spmm_csr(const int* __restrict__ rp, const int* __restrict__ pc,
                           const float* __restrict__ pv,
                           const float* __restrict__ X, float* __restrict__ Y, int nrows) {
    int r = (blockIdx.x * blockDim.x + threadIdx.x) >> 5;
    int d = threadIdx.x & 31;
    if (r >= nrows) return;
    int s = rp[r], e = rp[r + 1];
    float a0 = 0.f, a1 = 0.f;
    int k = s;
    for (; k + 1 < e; k += 2) {
        int c0 = pc[k], c1 = pc[k + 1];
        float v0 = pv[k], v1 = pv[k + 1];
        a0 += v0 * X[(c0 >> 2) * 128 + (c0 & 3) * 32 + d];
        a1 += v1 * X[(c1 >> 2) * 128 + (c1 & 3) * 32 + d];
    }
    if (k < e) {
        int c = pc[k];
        a0 += pv[k] * X[(c >> 2) * 128 + (c & 3) * 32 + d];
    }
    Y[(r >> 2) * 128 + (r & 3) * 32 + d] = a0 + a1;
}

// ---------------- column stats over a [rows,128] tensor ----------------
__global__ void k_stats128(const float* __restrict__ X, int rows,
                           float* __restrict__ statp, int off) {
    int c = threadIdx.x;  // 128
    float s = 0.f, s2 = 0.f;
    for (int r = blockIdx.x; r < rows; r += gridDim.x) {
        float x = X[r * 128 + c];
        s += x; s2 += x * x;
    }
    atomicAdd(&statp[off + c], s);
    atomicAdd(&statp[256 + off + c], s2);
}

// ---------------- fused BN + bias-fold + GEMM + elu + stats ----------------
// 32-row tiles, double-buffered smem, register prefetch.
// out = (A*a) @ W + bias [+ V];  A = [L | R] split, each [rows,128]
template<int KT, bool ACC>
__global__ void __launch_bounds__(256)
k_gemm(const float* __restrict__ L, const float* __restrict__ R, int rows,
       const float* __restrict__ W, const float* __restrict__ bvec,
       const float* __restrict__ gamma, const float* __restrict__ beta,
       const float* __restrict__ statp_in, float invn,
       float* __restrict__ Vout, float* __restrict__ Eout,
       float* __restrict__ statp_out) {
    __shared__ __align__(16) float As[2][16][40];
    __shared__ __align__(16) float Bs[2][16][128];
    __shared__ float sSc[256];
    __shared__ float sT [256];
    __shared__ float sB [128];
    int tid = threadIdx.x;  // 256

    // prologue: BN fold (redundant per block)
    if (KT == 16 || tid < 128) {
        float mean = statp_in[tid] * invn;
        float var  = fmaxf(statp_in[256 + tid] * invn - mean * mean, 0.f);
        float a = gamma[tid] * rsqrtf(var + EPSBN);
        sSc[tid] = a;
        sT[tid]  = beta[tid] - mean * a;
    } else {
        sT[tid] = beta[tid];   // broadcast-avg columns: var==0 -> BN out == beta
    }
    __syncthreads();

    int row0 = blockIdx.x * 32;
    int wc = tid & 31, wr = tid >> 5;     // outputs: rows wr*4+i, cols wc*4+j
    float acc[4][4];
#pragma unroll
    for (int i = 0; i < 4; i++)
#pragma unroll
        for (int j = 0; j < 4; j++) acc[i][j] = 0.f;
    float biasAcc = 0.f;

    int am = tid >> 2, ak4 = (tid & 3) * 4;   // A loader (tid<128): 32 rows x 16 k
    int bk = tid >> 5, bc = (tid & 31) * 4;   // B loader: rows bk and bk+8
    float4 rA = make_float4(0.f, 0.f, 0.f, 0.f), rB0, rB1;

    auto loadRegs = [&](int t) {
        int k0 = t * 16;
        if (tid < 128) {
            const float* Ab = (KT == 16 && k0 >= 128) ? R : L;
            int r = row0 + am;
            rA = make_float4(0.f, 0.f, 0.f, 0.f);
            if (r < rows) rA = *(const float4*)&Ab[r * 128 + (k0 & 127) + ak4];
        }
        rB0 = *(const float4*)&W[(k0 + bk) * 128 + bc];
        rB1 = *(const float4*)&W[(k0 + 8 + bk) * 128 + bc];
    };
    auto storeSmem = [&](int t, int b) {
        int k0 = t * 16;
        if (tid < 128) {
            As[b][ak4 + 0][am] = rA.x * sSc[k0 + ak4 + 0];
            As[b][ak4 + 1][am] = rA.y * sSc[k0 + ak4 + 1];
            As[b][ak4 + 2][am] = rA.z * sSc[k0 + ak4 + 2];
            As[b][ak4 + 3][am] = rA.w * sSc[k0 + ak4 + 3];
        }
        *(float4*)&Bs[b][bk][bc]     = rB0;
        *(float4*)&Bs[b][8 + bk][bc] = rB1;
    };

    loadRegs(0);
    storeSmem(0, 0);
    __syncthreads();
#pragma unroll 1
    for (int t = 0; t < KT; t++) {
        int b = t & 1;
        if (t + 1 < KT) loadRegs(t + 1);
        if (tid < 128) {  // bias fold on resident W tile
            int k0 = t * 16;
#pragma unroll
            for (int k = 0; k < 16; k++) biasAcc += sT[k0 + k] * Bs[b][k][tid];
        }
#pragma unroll
        for (int k = 0; k < 16; k++) {
            float4 a4 = *(const float4*)&As[b][k][wr * 4];
            float4 b4 = *(const float4*)&Bs[b][k][wc * 4];
            acc[0][0] += a4.x * b4.x; acc[0][1] += a4.x * b4.y;
            acc[0][2] += a4.x * b4.z; acc[0][3] += a4.x * b4.w;
            acc[1][0] += a4.y * b4.x; acc[1][1] += a4.y * b4.y;
            acc[1][2] += a4.y * b4.z; acc[1][3] += a4.y * b4.w;
            acc[2][0] += a4.z * b4.x; acc[2][1] += a4.z * b4.y;
            acc[2][2] += a4.z * b4.z; acc[2][3] += a4.z * b4.w;
            acc[3][0] += a4.w * b4.x; acc[3][1] += a4.w * b4.y;
            acc[3][2] += a4.w * b4.z; acc[3][3] += a4.w * b4.w;
        }
        if (t + 1 < KT) storeSmem(t + 1, b ^ 1);
        __syncthreads();
    }

    // KT==8: bias contribution of (unused) W rows 128..255 with t = beta
    if (KT == 8 && tid < 128) {
#pragma unroll 4
        for (int c = 128; c < 256; c++) biasAcc += sT[c] * W[c * 128 + tid];
    }
    if (tid < 128) sB[tid] = biasAcc + bvec[tid];
    __syncthreads();

    // epilogue: bias (+accum), elu, per-column stats
    float s1v[4] = {0.f, 0.f, 0.f, 0.f};
    float s2v[4] = {0.f, 0.f, 0.f, 0.f};
#pragma unroll
    for (int i = 0; i < 4; i++) {
        int r = row0 + wr * 4 + i;
        if (r >= rows) continue;
#pragma unroll
        for (int j = 0; j < 4; j++) {
            int c = wc * 4 + j;
            float val = acc[i][j] + sB[c];
            if (ACC) {
                val += Vout[r * 128 + c];
                Vout[r * 128 + c] = val;
            }
            float e = eluf(val);
            Eout[r * 128 + c] = e;
            s1v[j] += e; s2v[j] += e * e;
        }
    }
    float* red1 = &Bs[0][0][0];   // 8 x 128
    float* red2 = &Bs[1][0][0];
#pragma unroll
    for (int j = 0; j < 4; j++) {
        red1[wr * 128 + wc * 4 + j] = s1v[j];
        red2[wr * 128 + wc * 4 + j] = s2v[j];
    }
    __syncthreads();
    if (tid < 128) {
        float s = 0.f;
#pragma unroll
        for (int w = 0; w < 8; w++) s += red1[w * 128 + tid];
        atomicAdd(&statp_out[tid], s);
    } else {
        int c = tid - 128;
        float s = 0.f;
#pragma unroll
        for (int w = 0; w < 8; w++) s += red2[w * 128 + c];
        atomicAdd(&statp_out[256 + c], s);
    }
}

// ---------------- final head ----------------
__global__ void k_head_prep(const float* __restrict__ gamma, const float* __restrict__ beta,
                            const float* __restrict__ Wout, const float* __restrict__ bout,
                            const float* __restrict__ statp, float invn) {
    __shared__ float sh[128];
    int c = threadIdx.x;  // 128
    float mean = statp[c] * invn;
    float var  = fmaxf(statp[256 + c] * invn - mean * mean, 0.f);
    float a = gamma[c] * rsqrtf(var + EPSBN);
    g_a[c] = a;
    sh[c] = (beta[c] - mean * a) * Wout[c];
    __syncthreads();
    for (int s = 64; s > 0; s >>= 1) {
        if (c < s) sh[c] += sh[c + s];
        __syncthreads();
    }
    if (c == 0) g_bout[0] = bout[0] + sh[0];
}

__global__ void k_final(const float* __restrict__ Wout, float* __restrict__ out) {
    int warp = (blockIdx.x * blockDim.x + threadIdx.x) >> 5;
    int lane = threadIdx.x & 31;
    if (warp >= NV) return;
    float s = 0.f;
#pragma unroll
    for (int q = 0; q < 4; q++) {
        int c = q * 32 + lane;
        s += g_v[warp * 128 + c] * g_a[c] * Wout[c];
    }
#pragma unroll
    for (int o = 16; o; o >>= 1) s += __shfl_xor_sync(0xffffffffu, s, o);
    if (lane == 0) out[warp] = eluf(s + g_bout[0]);
}

// ---------------- host orchestration ----------------
extern "C" void kernel_launch(void* const* d_in, const int* in_sizes, int n_in,
                              void* d_out, int out_size) {
    const float* inputs   = (const float*)d_in[0];
    // d_in[1] = mask: irrelevant (avg columns fold to beta exactly)
    const int*   Di_rows  = (const int*)d_in[2];
    const int*   Di_cols  = (const int*)d_in[3];
    const float* Di_vals  = (const float*)d_in[4];
    const int*   DiA_rows = (const int*)d_in[5];
    const int*   DiA_cols = (const int*)d_in[6];
    const float* DiA_vals = (const float*)d_in[7];
    const float* W_in  = (const float*)d_in[8];
    const float* b_in  = (const float*)d_in[9];
    const float* g0    = (const float*)d_in[10];
    const float* be0   = (const float*)d_in[11];
    const float* W0    = (const float*)d_in[12];
    const float* b0    = (const float*)d_in[13];
    const float* g1    = (const float*)d_in[14];
    const float* be1   = (const float*)d_in[15];
    const float* Wl1   = (const float*)d_in[16];
    const float* bl1   = (const float*)d_in[17];
    const float* g2    = (const float*)d_in[18];
    const float* be2   = (const float*)d_in[19];
    const float* W_out = (const float*)d_in[20];
    const float* b_out = (const float*)d_in[21];
    float* out = (float*)d_out;
    (void)in_sizes; (void)n_in; (void)out_size;

    float *p_v, *p_ev, *p_ef, *p_ex, *p_Dv, *p_DA, *p_stats;
    int *p_rp0, *p_rp1, *p_pc0, *p_pc1, *p_cnt;
    float *p_pv0, *p_pv1;
    cudaGetSymbolAddress((void**)&p_v,     g_v);
    cudaGetSymbolAddress((void**)&p_ev,    g_ev);
    cudaGetSymbolAddress((void**)&p_ef,    g_ef);
    cudaGetSymbolAddress((void**)&p_ex,    g_ex);
    cudaGetSymbolAddress((void**)&p_Dv,    g_Dv);
    cudaGetSymbolAddress((void**)&p_DA,    g_DA);
    cudaGetSymbolAddress((void**)&p_stats, g_stats);
    cudaGetSymbolAddress((void**)&p_rp0,   g_rp0);
    cudaGetSymbolAddress((void**)&p_rp1,   g_rp1);
    cudaGetSymbolAddress((void**)&p_pc0,   g_pc0);
    cudaGetSymbolAddress((void**)&p_pc1,   g_pc1);
    cudaGetSymbolAddress((void**)&p_pv0,   g_pv0);
    cudaGetSymbolAddress((void**)&p_pv1,   g_pv1);
    cudaGetSymbolAddress((void**)&p_cnt,   g_cnt);
    auto SB = [&](int i) { return p_stats + (size_t)i * 512; };

    const int GF = (NFC + 31) / 32;   // 313
    const int GN = (NV  + 31) / 32;   // 157
    const int GE = (NNZT + 255) / 256;
    const float INV_F = 1.0f / (float)NFC;
    const float INV_N = 1.0f / (float)NV;

    // replay-invariant init
    cudaMemsetAsync(p_stats, 0, (size_t)64 * 512 * sizeof(float));
    cudaMemsetAsync(p_ef, 0, (size_t)NFC * 128 * sizeof(float));   // f(0)=0 -> elu=0
    k_in<<<128, 128>>>(inputs, W_in, b_in, SB(1));

    // CSR builds (once per launch, used 15x each)
    cudaMemsetAsync(p_cnt, 0, (size_t)QF * sizeof(int));
    k_hist<<<GE, 256>>>(Di_rows, p_cnt);
    k_scan<<<1, 1024>>>(p_cnt, p_rp0, QF);
    k_scatter<<<GE, 256>>>(Di_rows, Di_cols, Di_vals, p_cnt, p_pc0, p_pv0);
    cudaMemsetAsync(p_cnt, 0, (size_t)QV * sizeof(int));
    k_hist<<<GE, 256>>>(DiA_rows, p_cnt);
    k_scan<<<1, 1024>>>(p_cnt, p_rp1, QV);
    k_scatter<<<GE, 256>>>(DiA_rows, DiA_cols, DiA_vals, p_cnt, p_pc1, p_pv1);

    for (int i = 0; i < LAYERS; i++) {
        const float* W0i  = W0  + (size_t)i * 256 * 128;
        const float* Wl1i = Wl1 + (size_t)i * 256 * 128;
        int c1 = 2 * i, c2 = 2 * i + 1;
        if ((i & 1) == 0) {
            // ---- DirResNet2 ----
            k_spmm_csr<<<(QF * 32 + 255) / 256, 256>>>(p_rp0, p_pc0, p_pv0, p_ev, p_Dv, QF);
            k_stats128<<<256, 128>>>(p_Dv, NFC, SB(c1), 128);
            k_gemm<16, false><<<GF, 256>>>(p_ef, p_Dv, NFC, W0i, b0 + i * 128,
                                           g0 + i * 256, be0 + i * 256, SB(c1), INV_F,
                                           nullptr, p_ef, SB(c1 + 4));
            k_spmm_csr<<<(QV * 32 + 255) / 256, 256>>>(p_rp1, p_pc1, p_pv1, p_ef, p_DA, QV);
            k_stats128<<<256, 128>>>(p_DA, NV, SB(c2), 128);
            k_gemm<16, true><<<GN, 256>>>(p_ev, p_DA, NV, Wl1i, bl1 + i * 128,
                                          g1 + i * 256, be1 + i * 256, SB(c2), INV_N,
                                          p_v, p_ev, SB(c2 + 1));
        } else {
            // ---- AvgResNet2 (avg columns folded; K halved) ----
            k_gemm<8, false><<<GN, 256>>>(p_ev, nullptr, NV, W0i, b0 + i * 128,
                                          g0 + i * 256, be0 + i * 256, SB(c1), INV_N,
                                          nullptr, p_ex, SB(c1 + 1));
            k_gemm<8, true><<<GN, 256>>>(p_ex, nullptr, NV, Wl1i, bl1 + i * 128,
                                         g1 + i * 256, be1 + i * 256, SB(c2), INV_N,
                                         p_v, p_ev, SB(c2 + 2));
        }
    }

    // final head: elu( BN(v) @ W_out + b_out )
    k_stats128<<<256, 128>>>(p_v, NV, SB(62), 0);
    k_head_prep<<<1, 128>>>(g2, be2, W_out, b_out, SB(62), INV_N);
    k_final<<<(NV * 32 + 255) / 256, 256>>>(W_out, out);
}

// round 6
// speedup vs baseline: 1.0090x; 1.0090x over previous
#include <cuda_runtime.h>
#include <math.h>

// Problem constants
#define NV    5000
#define NFC   10000
#define LAYERS 30
#define NNZT  480000
#define EPSBN 1e-5f

// ---------------- device scratch ----------------
__device__ __align__(16) float g_v [NV  * 128];  // vertex features (raw)
__device__ __align__(16) float g_ev[NV  * 128];  // elu(v)
__device__ __align__(16) float g_ef[NFC * 128];  // elu(f_out)
__device__ __align__(16) float g_ex[NV  * 128];  // odd-layer elu scratch
__device__ __align__(16) float g_Dv[NFC * 128];  // Dirac vertices->faces
__device__ __align__(16) float g_DA[NV  * 128];  // adjoint Dirac faces->vertices
__device__ float g_stats[64 * 512];              // one-shot stat buffers: sum[256]|sumsq[256]
__device__ float g_a   [128];                    // head BN scale
__device__ float g_bout[1];                      // head scalar bias

__device__ __forceinline__ float eluf(float x) {
    return x > 0.f ? x : (__expf(x) - 1.f);
}

// ---------------- input projection: v = in @ W_in + b; ev = elu(v); stats(ev) ----
__global__ void k_in(const float* __restrict__ in, const float* __restrict__ Wi,
                     const float* __restrict__ bi, float* __restrict__ statp) {
    int c = threadIdx.x;  // 128
    float w0 = Wi[c], w1 = Wi[128 + c], w2 = Wi[256 + c], b = bi[c];
    float s = 0.f, s2 = 0.f;
    for (int n = blockIdx.x; n < NV; n += gridDim.x) {
        float val = b + in[n * 3] * w0 + in[n * 3 + 1] * w1 + in[n * 3 + 2] * w2;
        g_v [n * 128 + c] = val;
        float e = eluf(val);
        g_ev[n * 128 + c] = e;
        s += e; s2 += e * e;
    }
    atomicAdd(&statp[c], s);
    atomicAdd(&statp[256 + c], s2);
}

// ---------------- COO spMM: 8 threads/edge, float4 vector atomics ----------------
__global__ void k_spmm(const int* __restrict__ rows_, const int* __restrict__ cols_,
                       const float* __restrict__ vals,
                       const float* __restrict__ X, float* __restrict__ Y) {
    int idx = blockIdx.x * blockDim.x + threadIdx.x;
    int e = idx >> 3, d = idx & 7;
    if (e >= NNZT) return;
    int R = rows_[e], Cq = cols_[e];
    float v = vals[e];
    float4 xv = ((const float4*)X)[(Cq >> 2) * 32 + (Cq & 3) * 8 + d];
    float4* yp = (float4*)Y + (R >> 2) * 32 + (R & 3) * 8 + d;
    asm volatile("red.global.add.v4.f32 [%0], {%1,%2,%3,%4};"
                 :: "l"(yp), "f"(v * xv.x), "f"(v * xv.y), "f"(v * xv.z), "f"(v * xv.w)
                 : "memory");
}

// ---------------- column stats over a [rows,128] tensor ----------------
__global__ void k_stats128(const float* __restrict__ X, int rows,
                           float* __restrict__ statp, int off) {
    int c = threadIdx.x;  // 128
    float s = 0.f, s2 = 0.f;
    for (int r = blockIdx.x; r < rows; r += gridDim.x) {
        float x = X[r * 128 + c];
        s += x; s2 += x * x;
    }
    atomicAdd(&statp[off + c], s);
    atomicAdd(&statp[256 + off + c], s2);
}

// ---------------- fused BN-fold + bias-fold + GEMM + elu + stats ----------------
// 64-row tiles, double-buffered smem, register prefetch, float4 A-fragments.
// out = (A*a) @ W + bias [+ V];  A = [L | R] split pointers, each [rows,128]
// KT=16 -> K=256; KT=8 -> K=128 (right half folds to beta)
template<int KT, bool ACC>
__global__ void __launch_bounds__(256)
k_gemm(const float* __restrict__ L, const float* __restrict__ R, int rows,
       const float* __restrict__ W, const float* __restrict__ bvec,
       const float* __restrict__ gamma, const float* __restrict__ beta,
       const float* __restrict__ statp_in, float invn,
       float* __restrict__ Vout, float* __restrict__ Eout,
       float* __restrict__ statp_out) {
    __shared__ __align__(16) float As[2][16][72];   // stride 72: float4-aligned rows
    __shared__ __align__(16) float Bs[2][16][128];
    __shared__ float sSc[256];
    __shared__ float sT [256];
    __shared__ float sB [128];
    int tid = threadIdx.x;  // 256

    // prologue: BN fold (redundant per block, ~1KB reads)
    if (KT == 16 || tid < 128) {
        float mean = statp_in[tid] * invn;
        float var  = fmaxf(statp_in[256 + tid] * invn - mean * mean, 0.f);
        float a = gamma[tid] * rsqrtf(var + EPSBN);
        sSc[tid] = a;
        sT[tid]  = beta[tid] - mean * a;
    } else {
        sT[tid] = beta[tid];   // broadcast-avg columns: var==0 -> BN out == beta
    }
    __syncthreads();

    int row0 = blockIdx.x * 64;
    int wc = tid & 31, wr = tid >> 5;   // outputs: rows wr*8+i, cols wc*4+j
    float acc[8][4];
#pragma unroll
    for (int i = 0; i < 8; i++)
#pragma unroll
        for (int j = 0; j < 4; j++) acc[i][j] = 0.f;
    float biasAcc = 0.f;

    int am = tid >> 2, ak4 = (tid & 3) * 4;   // A loader: 64 rows x 16 k, float4 each
    int bk = tid >> 5, bc = (tid & 31) * 4;   // B loader: rows bk and bk+8
    float4 rA, rB0, rB1;

    auto loadRegs = [&](int t) {
        int k0 = t * 16;
        const float* Ab = (KT == 16 && k0 >= 128) ? R : L;
        int r = row0 + am;
        rA = make_float4(0.f, 0.f, 0.f, 0.f);
        if (r < rows) rA = *(const float4*)&Ab[r * 128 + (k0 & 127) + ak4];
        rB0 = *(const float4*)&W[(k0 + bk) * 128 + bc];
        rB1 = *(const float4*)&W[(k0 + 8 + bk) * 128 + bc];
    };
    auto storeSmem = [&](int t, int b) {
        int k0 = t * 16;
        As[b][ak4 + 0][am] = rA.x * sSc[k0 + ak4 + 0];
        As[b][ak4 + 1][am] = rA.y * sSc[k0 + ak4 + 1];
        As[b][ak4 + 2][am] = rA.z * sSc[k0 + ak4 + 2];
        As[b][ak4 + 3][am] = rA.w * sSc[k0 + ak4 + 3];
        *(float4*)&Bs[b][bk][bc]     = rB0;
        *(float4*)&Bs[b][8 + bk][bc] = rB1;
    };

    loadRegs(0);
    storeSmem(0, 0);
    __syncthreads();
#pragma unroll 1
    for (int t = 0; t < KT; t++) {
        int b = t & 1;
        if (t + 1 < KT) loadRegs(t + 1);   // prefetch next tile (hides LDG latency)
        if (tid < 128) {                    // bias fold on resident W tile
            int k0 = t * 16;
#pragma unroll
            for (int k = 0; k < 16; k++) biasAcc += sT[k0 + k] * Bs[b][k][tid];
        }
#pragma unroll
        for (int k = 0; k < 16; k++) {
            float4 a0 = *(const float4*)&As[b][k][wr * 8];       // broadcast within warp
            float4 a1 = *(const float4*)&As[b][k][wr * 8 + 4];
            float4 b4 = *(const float4*)&Bs[b][k][wc * 4];
            acc[0][0] += a0.x * b4.x; acc[0][1] += a0.x * b4.y;
            acc[0][2] += a0.x * b4.z; acc[0][3] += a0.x * b4.w;
            acc[1][0] += a0.y * b4.x; acc[1][1] += a0.y * b4.y;
            acc[1][2] += a0.y * b4.z; acc[1][3] += a0.y * b4.w;
            acc[2][0] += a0.z * b4.x; acc[2][1] += a0.z * b4.y;
            acc[2][2] += a0.z * b4.z; acc[2][3] += a0.z * b4.w;
            acc[3][0] += a0.w * b4.x; acc[3][1] += a0.w * b4.y;
            acc[3][2] += a0.w * b4.z; acc[3][3] += a0.w * b4.w;
            acc[4][0] += a1.x * b4.x; acc[4][1] += a1.x * b4.y;
            acc[4][2] += a1.x * b4.z; acc[4][3] += a1.x * b4.w;
            acc[5][0] += a1.y * b4.x; acc[5][1] += a1.y * b4.y;
            acc[5][2] += a1.y * b4.z; acc[5][3] += a1.y * b4.w;
            acc[6][0] += a1.z * b4.x; acc[6][1] += a1.z * b4.y;
            acc[6][2] += a1.z * b4.z; acc[6][3] += a1.z * b4.w;
            acc[7][0] += a1.w * b4.x; acc[7][1] += a1.w * b4.y;
            acc[7][2] += a1.w * b4.z; acc[7][3] += a1.w * b4.w;
        }
        if (t + 1 < KT) storeSmem(t + 1, b ^ 1);  // safe: buffer b^1 last read before prev barrier
        __syncthreads();
    }

    // KT==8: bias contribution of folded-away W rows 128..255 (t = beta there)
    if (KT == 8 && tid < 128) {
#pragma unroll 4
        for (int c = 128; c < 256; c++) biasAcc += sT[c] * W[c * 128 + tid];
    }
    if (tid < 128) sB[tid] = biasAcc + bvec[tid];
    __syncthreads();

    // epilogue: bias (+accum), elu, per-column stats
    float s1v[4] = {0.f, 0.f, 0.f, 0.f};
    float s2v[4] = {0.f, 0.f, 0.f, 0.f};
#pragma unroll
    for (int i = 0; i < 8; i++) {
        int r = row0 + wr * 8 + i;
        if (r >= rows) continue;
#pragma unroll
        for (int j = 0; j < 4; j++) {
            int c = wc * 4 + j;
            float val = acc[i][j] + sB[c];
            if (ACC) {
                val += Vout[r * 128 + c];
                Vout[r * 128 + c] = val;
            }
            float e = eluf(val);
            Eout[r * 128 + c] = e;
            s1v[j] += e; s2v[j] += e * e;
        }
    }
    float* red1 = &Bs[0][0][0];   // 8 warps x 128
    float* red2 = &Bs[1][0][0];
#pragma unroll
    for (int j = 0; j < 4; j++) {
        red1[wr * 128 + wc * 4 + j] = s1v[j];
        red2[wr * 128 + wc * 4 + j] = s2v[j];
    }
    __syncthreads();
    if (tid < 128) {
        float s = 0.f;
#pragma unroll
        for (int w = 0; w < 8; w++) s += red1[w * 128 + tid];
        atomicAdd(&statp_out[tid], s);
    } else {
        int c = tid - 128;
        float s = 0.f;
#pragma unroll
        for (int w = 0; w < 8; w++) s += red2[w * 128 + c];
        atomicAdd(&statp_out[256 + c], s);
    }
}

// ---------------- final head ----------------
__global__ void k_head_prep(const float* __restrict__ gamma, const float* __restrict__ beta,
                            const float* __restrict__ Wout, const float* __restrict__ bout,
                            const float* __restrict__ statp, float invn) {
    __shared__ float sh[128];
    int c = threadIdx.x;  // 128
    float mean = statp[c] * invn;
    float var  = fmaxf(statp[256 + c] * invn - mean * mean, 0.f);
    float a = gamma[c] * rsqrtf(var + EPSBN);
    g_a[c] = a;
    sh[c] = (beta[c] - mean * a) * Wout[c];
    __syncthreads();
    for (int s = 64; s > 0; s >>= 1) {
        if (c < s) sh[c] += sh[c + s];
        __syncthreads();
    }
    if (c == 0) g_bout[0] = bout[0] + sh[0];
}

__global__ void k_final(const float* __restrict__ Wout, float* __restrict__ out) {
    int warp = (blockIdx.x * blockDim.x + threadIdx.x) >> 5;
    int lane = threadIdx.x & 31;
    if (warp >= NV) return;
    float s = 0.f;
#pragma unroll
    for (int q = 0; q < 4; q++) {
        int c = q * 32 + lane;
        s += g_v[warp * 128 + c] * g_a[c] * Wout[c];
    }
#pragma unroll
    for (int o = 16; o; o >>= 1) s += __shfl_xor_sync(0xffffffffu, s, o);
    if (lane == 0) out[warp] = eluf(s + g_bout[0]);
}

// ---------------- host orchestration ----------------
extern "C" void kernel_launch(void* const* d_in, const int* in_sizes, int n_in,
                              void* d_out, int out_size) {
    const float* inputs   = (const float*)d_in[0];
    // d_in[1] = mask: irrelevant (avg columns fold to beta exactly)
    const int*   Di_rows  = (const int*)d_in[2];
    const int*   Di_cols  = (const int*)d_in[3];
    const float* Di_vals  = (const float*)d_in[4];
    const int*   DiA_rows = (const int*)d_in[5];
    const int*   DiA_cols = (const int*)d_in[6];
    const float* DiA_vals = (const float*)d_in[7];
    const float* W_in  = (const float*)d_in[8];
    const float* b_in  = (const float*)d_in[9];
    const float* g0    = (const float*)d_in[10];
    const float* be0   = (const float*)d_in[11];
    const float* W0    = (const float*)d_in[12];
    const float* b0    = (const float*)d_in[13];
    const float* g1    = (const float*)d_in[14];
    const float* be1   = (const float*)d_in[15];
    const float* Wl1   = (const float*)d_in[16];
    const float* bl1   = (const float*)d_in[17];
    const float* g2    = (const float*)d_in[18];
    const float* be2   = (const float*)d_in[19];
    const float* W_out = (const float*)d_in[20];
    const float* b_out = (const float*)d_in[21];
    float* out = (float*)d_out;
    (void)in_sizes; (void)n_in; (void)out_size;

    float *p_v, *p_ev, *p_ef, *p_ex, *p_Dv, *p_DA, *p_stats;
    cudaGetSymbolAddress((void**)&p_v,     g_v);
    cudaGetSymbolAddress((void**)&p_ev,    g_ev);
    cudaGetSymbolAddress((void**)&p_ef,    g_ef);
    cudaGetSymbolAddress((void**)&p_ex,    g_ex);
    cudaGetSymbolAddress((void**)&p_Dv,    g_Dv);
    cudaGetSymbolAddress((void**)&p_DA,    g_DA);
    cudaGetSymbolAddress((void**)&p_stats, g_stats);
    auto SB = [&](int i) { return p_stats + (size_t)i * 512; };

    const int GF = (NFC + 63) / 64;   // 157
    const int GN = (NV  + 63) / 64;   // 79
    const int GS = (NNZT * 8 + 255) / 256;
    const float INV_F = 1.0f / (float)NFC;
    const float INV_N = 1.0f / (float)NV;

    // replay-invariant init
    cudaMemsetAsync(p_stats, 0, (size_t)64 * 512 * sizeof(float));
    cudaMemsetAsync(p_ef, 0, (size_t)NFC * 128 * sizeof(float));   // f(0)=0 -> elu=0
    k_in<<<128, 128>>>(inputs, W_in, b_in, SB(1));

    for (int i = 0; i < LAYERS; i++) {
        const float* W0i  = W0  + (size_t)i * 256 * 128;
        const float* Wl1i = Wl1 + (size_t)i * 256 * 128;
        int c1 = 2 * i, c2 = 2 * i + 1;
        if ((i & 1) == 0) {
            // ---- DirResNet2 ----
            cudaMemsetAsync(p_Dv, 0, (size_t)NFC * 128 * sizeof(float));
            k_spmm<<<GS, 256>>>(Di_rows, Di_cols, Di_vals, p_ev, p_Dv);
            k_stats128<<<256, 128>>>(p_Dv, NFC, SB(c1), 128);
            k_gemm<16, false><<<GF, 256>>>(p_ef, p_Dv, NFC, W0i, b0 + i * 128,
                                           g0 + i * 256, be0 + i * 256, SB(c1), INV_F,
                                           nullptr, p_ef, SB(c1 + 4));
            cudaMemsetAsync(p_DA, 0, (size_t)NV * 128 * sizeof(float));
            k_spmm<<<GS, 256>>>(DiA_rows, DiA_cols, DiA_vals, p_ef, p_DA);
            k_stats128<<<256, 128>>>(p_DA, NV, SB(c2), 128);
            k_gemm<16, true><<<GN, 256>>>(p_ev, p_DA, NV, Wl1i, bl1 + i * 128,
                                          g1 + i * 256, be1 + i * 256, SB(c2), INV_N,
                                          p_v, p_ev, SB(c2 + 1));
        } else {
            // ---- AvgResNet2 (avg columns folded; K halved) ----
            k_gemm<8, false><<<GN, 256>>>(p_ev, nullptr, NV, W0i, b0 + i * 128,
                                          g0 + i * 256, be0 + i * 256, SB(c1), INV_N,
                                          nullptr, p_ex, SB(c1 + 1));
            k_gemm<8, true><<<GN, 256>>>(p_ex, nullptr, NV, Wl1i, bl1 + i * 128,
                                         g1 + i * 256, be1 + i * 256, SB(c2), INV_N,
                                         p_v, p_ev, SB(c2 + 2));
        }
    }

    // final head: elu( BN(v) @ W_out + b_out )
    k_stats128<<<256, 128>>>(p_v, NV, SB(62), 0);
    k_head_prep<<<1, 128>>>(g2, be2, W_out, b_out, SB(62), INV_N);
    k_final<<<(NV * 32 + 255) / 256, 256>>>(W_out, out);
}